// round 2
// baseline (speedup 1.0000x reference)
#include <cuda_runtime.h>
#include <cstdint>
#include <cstddef>

// Problem constants
#define B_  32
#define I_  2048
#define KK  16
#define J_  64
#define D_  32

#define WARPS  4
#define IPW    8                 // i handled per warp (sequential)
#define IC     (WARPS * IPW)     // 32 i per block
#define NCHUNK (I_ / IC)         // 64 chunks
#define SLAB   (B_ * J_ * D_)    // 65536

// Scratch (no allocations allowed -> device globals)
__device__ float g_b_log[(size_t)B_ * I_ * J_];          // routing logits [b][i][j], 16 MB
__device__ float g_s_part[(size_t)NCHUNK * SLAB];        // per-chunk partial s, 16 MB
__device__ float g_v[SLAB];                              // current v [b][j][d]

// Shared memory layout (floats):
//   u_s : [WARPS][J_][33]   (padded, conflict-free in both access patterns)
//   v_s : [J_][33]
//   c_s : [WARPS][J_]
//   x_s : [IC][KK]
// total = 4*64*33 + 64*33 + 4*64 + 32*16 = 11328 floats = 45312 bytes  (< 48KB,
// so no cudaFuncSetAttribute needed)
#define U_OFF 0
#define V_OFF (WARPS * J_ * 33)
#define C_OFF (V_OFF + J_ * 33)
#define X_OFF (C_OFF + WARPS * J_)
#define SMEM_FLOATS (X_OFF + IC * KK)

__device__ __forceinline__ float dot16(const float4* __restrict__ p, const float* xr)
{
    float4 a0 = p[0], a1 = p[1], a2 = p[2], a3 = p[3];
    float u0 = a0.x * xr[0];
    float u1 = a0.y * xr[1];
    u0 = fmaf(a0.z, xr[2],  u0);
    u1 = fmaf(a0.w, xr[3],  u1);
    u0 = fmaf(a1.x, xr[4],  u0);
    u1 = fmaf(a1.y, xr[5],  u1);
    u0 = fmaf(a1.z, xr[6],  u0);
    u1 = fmaf(a1.w, xr[7],  u1);
    u0 = fmaf(a2.x, xr[8],  u0);
    u1 = fmaf(a2.y, xr[9],  u1);
    u0 = fmaf(a2.z, xr[10], u0);
    u1 = fmaf(a2.w, xr[11], u1);
    u0 = fmaf(a3.x, xr[12], u0);
    u1 = fmaf(a3.y, xr[13], u1);
    u0 = fmaf(a3.z, xr[14], u0);
    u1 = fmaf(a3.w, xr[15], u1);
    return u0 + u1;
}

// MODE 0: r=0  (c uniform = 1/J; no logits, no v)       -> partial s
// MODE 1: r=1  (t = dot(v0,u);   write logits; softmax) -> partial s
// MODE 2: r=2  (t = logits + dot(v1,u); softmax)        -> partial s
template <int MODE>
__global__ __launch_bounds__(WARPS * 32)
void route_kernel(const float* __restrict__ x, const float* __restrict__ W)
{
    __shared__ float sm[SMEM_FLOATS];
    float* u_s = sm + U_OFF;
    float* v_s = sm + V_OFF;
    float* c_s = sm + C_OFF;
    float* x_s = sm + X_OFF;

    const int tid   = threadIdx.x;
    const int w     = tid >> 5;
    const int l     = tid & 31;
    const int b     = blockIdx.x & (B_ - 1);
    const int chunk = blockIdx.x >> 5;         // consecutive blocks share chunk -> L2 reuse of W
    const int i0    = chunk * IC;

    // stage x[b, i0 : i0+IC, :] (512 floats)
    {
        const float* xp = x + ((size_t)b * I_ + i0) * KK;
        for (int t = tid; t < IC * KK; t += WARPS * 32) x_s[t] = xp[t];
    }
    // stage v[b, :, :] (2048 floats) with padding
    if (MODE != 0) {
        const float* vp = g_v + (size_t)b * J_ * D_;
        for (int t = tid; t < J_ * D_; t += WARPS * 32) {
            int j = t >> 5, d = t & 31;
            v_s[j * 33 + d] = vp[t];
        }
    }
    __syncthreads();

    float s_acc[J_];
    #pragma unroll
    for (int j = 0; j < J_; j++) s_acc[j] = 0.f;

    float* u_w = u_s + w * (J_ * 33);
    float* c_w = c_s + w * J_;

    for (int ii = 0; ii < IPW; ii++) {
        const int iloc = w * IPW + ii;
        const int i    = i0 + iloc;

        float xr[KK];
        #pragma unroll
        for (int k = 0; k < KK; k++) xr[k] = x_s[iloc * KK + k];

        const float4* Wp = reinterpret_cast<const float4*>(
            W + ((size_t)i * D_ + l) * KK);
        const size_t jstr4 = (size_t)I_ * D_ * KK / 4;   // float4 stride per j

        __syncwarp();   // u_w free for reuse (prev phase D done)

        // ---- phase A: u[j][lane=d] = sum_k W[j,i,d,k] * x[b,i,k] ----
        #pragma unroll 2
        for (int j = 0; j < J_; j++) {
            float u = dot16(Wp + (size_t)j * jstr4, xr);
            u_w[j * 33 + l] = u;
        }
        __syncwarp();

        // ---- phase B/C: logits + softmax over j (lanes parallel over j) ----
        if (MODE != 0) {
            const int jA = l, jB = l + 32;
            float tA = 0.f, tB = 0.f;
            #pragma unroll
            for (int d = 0; d < D_; d++) {
                tA = fmaf(v_s[jA * 33 + d], u_w[jA * 33 + d], tA);
                tB = fmaf(v_s[jB * 33 + d], u_w[jB * 33 + d], tB);
            }
            float* bp = g_b_log + ((size_t)b * I_ + i) * J_;
            if (MODE == 2) { tA += bp[jA]; tB += bp[jB]; }
            if (MODE == 1) { bp[jA] = tA;  bp[jB] = tB; }

            float m = fmaxf(tA, tB);
            #pragma unroll
            for (int off = 16; off; off >>= 1)
                m = fmaxf(m, __shfl_xor_sync(0xffffffffu, m, off));
            float eA = __expf(tA - m);
            float eB = __expf(tB - m);
            float sum = eA + eB;
            #pragma unroll
            for (int off = 16; off; off >>= 1)
                sum += __shfl_xor_sync(0xffffffffu, sum, off);
            float inv = __fdividef(1.f, sum);
            c_w[jA] = eA * inv;
            c_w[jB] = eB * inv;
            __syncwarp();
        }

        // ---- phase D: s[j][d] += c[j] * u[j][d] ----
        if (MODE == 0) {
            #pragma unroll
            for (int j = 0; j < J_; j++)
                s_acc[j] += u_w[j * 33 + l];
        } else {
            #pragma unroll
            for (int j = 0; j < J_; j++)
                s_acc[j] = fmaf(c_w[j], u_w[j * 33 + l], s_acc[j]);
        }
    }

    // ---- cross-warp reduction of s (reuse u_s as staging) ----
    __syncthreads();
    {
        const float scale = (MODE == 0) ? (1.f / (float)J_) : 1.f;
        #pragma unroll
        for (int j = 0; j < J_; j++) u_w[j * 33 + l] = s_acc[j] * scale;
    }
    __syncthreads();
    for (int step = WARPS / 2; step > 0; step >>= 1) {
        if (w < step) {
            float* a  = u_s + (size_t)w * (J_ * 33);
            float* bb = u_s + (size_t)(w + step) * (J_ * 33);
            #pragma unroll
            for (int j = 0; j < J_; j++) a[j * 33 + l] += bb[j * 33 + l];
        }
        __syncthreads();
    }
    // warp w writes its J_/WARPS j's (plain stores -> deterministic)
    {
        float* sp = g_s_part + (size_t)chunk * SLAB + (size_t)b * J_ * D_;
        #pragma unroll
        for (int jj = 0; jj < J_ / WARPS; jj++) {
            int j = w * (J_ / WARPS) + jj;
            sp[j * D_ + l] = u_s[j * 33 + l];
        }
    }
}

// Sum the 64 chunk partials, squash, write v (and final output).
__global__ __launch_bounds__(256)
void squash_kernel(float* __restrict__ out)
{
    const int tid = threadIdx.x;
    const int w   = tid >> 5;
    const int l   = tid & 31;
    const int bj  = blockIdx.x * 8 + w;      // 0 .. B_*J_-1   (grid = 256)

    float s = 0.f;
    const float* p = g_s_part + (size_t)bj * D_ + l;
    #pragma unroll
    for (int ch = 0; ch < NCHUNK; ch++) s += p[(size_t)ch * SLAB];

    float sq = s * s;
    #pragma unroll
    for (int off = 16; off; off >>= 1)
        sq += __shfl_xor_sync(0xffffffffu, sq, off);

    float scale = sq / ((1.f + sq) * sqrtf(sq + 1e-7f));
    float v = scale * s;

    g_v[(size_t)bj * D_ + l] = v;
    if (out) out[(size_t)bj * D_ + l] = v;
}

extern "C" void kernel_launch(void* const* d_in, const int* in_sizes, int n_in,
                              void* d_out, int out_size)
{
    const float* x;
    const float* W;
    if (in_sizes[0] == B_ * I_ * KK) {
        x = (const float*)d_in[0];
        W = (const float*)d_in[1];
    } else {
        x = (const float*)d_in[1];
        W = (const float*)d_in[0];
    }
    float* out = (float*)d_out;

    const dim3 grid(B_ * NCHUNK);   // 2048 blocks; consecutive blocks share W chunk
    const dim3 blk(WARPS * 32);     // 128 threads

    route_kernel<0><<<grid, blk>>>(x, W);   // r=0: uniform c
    squash_kernel<<<256, 256>>>(nullptr);   // v0

    route_kernel<1><<<grid, blk>>>(x, W);   // r=1: logits = dot(v0,u), softmax
    squash_kernel<<<256, 256>>>(nullptr);   // v1

    route_kernel<2><<<grid, blk>>>(x, W);   // r=2: logits += dot(v1,u), softmax
    squash_kernel<<<256, 256>>>(out);       // v2 -> output
}

// round 3
// speedup vs baseline: 4.5051x; 4.5051x over previous
#include <cuda_runtime.h>
#include <cstdint>
#include <cstddef>

// Problem constants
#define B_  32
#define I_  2048
#define KK  16
#define J_  64
#define D_  32

#define BG      8                  // batches per block
#define NBG     (B_ / BG)          // 4 b-groups
#define IC      32                 // i per block
#define NCHUNK  (I_ / IC)          // 64
#define SLAB    (B_ * J_ * D_)     // 65536
#define THREADS 256

// Shared memory layout (float offsets)
//   W  : 2 buffers x [16 j][32 d][16 k] (quad-swizzled)  = 16384 floats (64 KB)
//   x  : [BG][IC][KK]                                    =  4096 floats (16 KB)
//   c  : [BG][J_]                                        =   512 floats ( 2 KB)
//   v  : [BG][J_][D_]  (d ^ (j&31) swizzle)              = 16384 floats (64 KB)
//   u  : [BG][J_][D_]  (d ^ (j&31) swizzle)              = 16384 floats (64 KB)
#define OFF_W 0
#define OFF_X 16384
#define OFF_C 20480
#define OFF_V 20992
#define OFF_U 37376
#define SMB_FULL ((OFF_U + BG * J_ * D_) * 4)   // 215040 B
#define SMB_M0   ((OFF_C + BG * J_) * 4)        //  83968 B

// Scratch (device globals; no allocations allowed)
__device__ float g_b_log[(size_t)B_ * I_ * J_];   // routing logits [b][i][j]
__device__ float g_s_part[(size_t)NCHUNK * SLAB]; // per-chunk partial s
__device__ float g_v[SLAB];                       // current v [b][j][d]

__device__ __forceinline__ void cp16(float* dst, const float4* src) {
    unsigned s = (unsigned)__cvta_generic_to_shared(dst);
    asm volatile("cp.async.cg.shared.global [%0], [%1], 16;\n" :: "r"(s), "l"(src));
}
__device__ __forceinline__ void cp_commit() { asm volatile("cp.async.commit_group;\n" ::); }
__device__ __forceinline__ void cp_wait0()  { asm volatile("cp.async.wait_group 0;\n" ::); }

// Stage one quarter of W[:, i_abs, :, :] (16 j) into W_s buffer `buf`.
// Swizzle: quad index kq ^ ((d>>1)&3)  -> conflict-free LDS.128 in compute.
__device__ __forceinline__ void issue_quarter(float* W_s, const float4* Wg4,
                                              int i_abs, int q, int buf, int tid)
{
    float* dstbase = W_s + buf * 8192;
    #pragma unroll
    for (int r = 0; r < 8; r++) {
        int n    = tid + (r << 8);      // 0..2047 float4s
        int jloc = n >> 7;              // 0..15
        int d    = (n >> 2) & 31;
        int kq   = n & 3;
        int jg   = q * 16 + jloc;
        const float4* src = Wg4 + ((((size_t)jg * I_ + i_abs) * 32 + d) * 4 + kq);
        float* dst = dstbase + ((jloc * 32 + d) * 4 + (kq ^ ((d >> 1) & 3))) * 4;
        cp16(dst, src);
    }
    cp_commit();
}

// MODE 0: r=0 uniform coupling. MODE 1: logits = dot(v,u), store. MODE 2: logits += dot(v,u).
template <int MODE>
__global__ __launch_bounds__(THREADS)
void route_kernel(const float* __restrict__ x, const float* __restrict__ W)
{
    extern __shared__ float sm[];
    float* W_s = sm + OFF_W;
    float* x_s = sm + OFF_X;
    float* c_s = sm + OFF_C;
    float* v_s = sm + OFF_V;
    float* u_s = sm + OFF_U;

    const int tid   = threadIdx.x;
    const int w     = tid >> 5;
    const int l     = tid & 31;
    const int g     = blockIdx.x & (NBG - 1);
    const int chunk = blockIdx.x >> 2;
    const int i0    = chunk * IC;
    const int b0    = g * BG;

    const float4* Wg4 = reinterpret_cast<const float4*>(W);

    // Prologue: start loading quarter 0 of the first i
    issue_quarter(W_s, Wg4, i0, 0, 0, tid);

    // Stage x[b0:b0+BG, i0:i0+IC, :]
    for (int n = tid; n < BG * IC * KK; n += THREADS) {
        int b = n >> 9;                 // 512 floats per b
        int r = n & 511;
        x_s[n] = x[((size_t)(b0 + b) * I_ + i0) * KK + r];
    }
    // Stage v[b0:b0+BG, :, :] with d ^ (j&31) swizzle
    if (MODE != 0) {
        for (int n = tid; n < BG * J_ * D_; n += THREADS) {
            int b = n >> 11;
            int j = (n >> 5) & 63;
            int d = n & 31;
            v_s[(b * J_ + j) * D_ + (d ^ (j & 31))] =
                g_v[(size_t)(b0 + b) * J_ * D_ + (n & 2047)];
        }
    }
    __syncthreads();

    float s_acc[BG][8];
    #pragma unroll
    for (int b = 0; b < BG; b++)
        #pragma unroll
        for (int jj = 0; jj < 8; jj++) s_acc[b][jj] = 0.f;

    for (int ii = 0; ii < IC; ii++) {
        const int i_abs = i0 + ii;

        #pragma unroll
        for (int q = 0; q < 4; q++) {
            cp_wait0();
            __syncthreads();            // quarter q visible; prev compute done
            if (q < 3)                  issue_quarter(W_s, Wg4, i_abs,     q + 1, (q + 1) & 1, tid);
            else if (ii + 1 < IC)       issue_quarter(W_s, Wg4, i_abs + 1, 0,     0,           tid);

            // ---- phase A on buffer q&1: u[b][j][d=lane] for j = q*16 + w*2 + e ----
            const float* Wb = W_s + (q & 1) * 8192;
            float ur[BG][2];
            #pragma unroll
            for (int b = 0; b < BG; b++) { ur[b][0] = 0.f; ur[b][1] = 0.f; }

            #pragma unroll
            for (int qk = 0; qk < 4; qk++) {
                float4 xq[BG];
                #pragma unroll
                for (int b = 0; b < BG; b++)
                    xq[b] = *reinterpret_cast<const float4*>(
                        &x_s[(b * IC + ii) * KK + qk * 4]);
                #pragma unroll
                for (int e = 0; e < 2; e++) {
                    int jloc = w * 2 + e;
                    float4 Wq = *reinterpret_cast<const float4*>(
                        &Wb[((jloc * 32 + l) * 4 + (qk ^ ((l >> 1) & 3))) * 4]);
                    #pragma unroll
                    for (int b = 0; b < BG; b++) {
                        ur[b][e] = fmaf(Wq.x, xq[b].x, ur[b][e]);
                        ur[b][e] = fmaf(Wq.y, xq[b].y, ur[b][e]);
                        ur[b][e] = fmaf(Wq.z, xq[b].z, ur[b][e]);
                        ur[b][e] = fmaf(Wq.w, xq[b].w, ur[b][e]);
                    }
                }
            }

            if (MODE == 0) {
                #pragma unroll
                for (int e = 0; e < 2; e++)
                    #pragma unroll
                    for (int b = 0; b < BG; b++)
                        s_acc[b][q * 2 + e] += ur[b][e];
            } else {
                #pragma unroll
                for (int e = 0; e < 2; e++) {
                    int j = q * 16 + w * 2 + e;
                    #pragma unroll
                    for (int b = 0; b < BG; b++)
                        u_s[(b * J_ + j) * D_ + (l ^ (j & 31))] = ur[b][e];
                }
            }
        }

        if (MODE != 0) {
            __syncthreads();            // u_s complete for all 64 j

            // ---- phase B: warp w owns batch b=w; lanes = j and j+32 ----
            {
                const int b = w;
                const int jA = l, jB = l + 32;
                const int baseA = (b * J_ + jA) * D_;
                const int baseB = (b * J_ + jB) * D_;
                float t0 = 0.f, t1 = 0.f;
                #pragma unroll
                for (int d = 0; d < D_; d++) {
                    int iA = baseA + (d ^ (jA & 31));
                    int iB = baseB + (d ^ (jB & 31));
                    t0 = fmaf(v_s[iA], u_s[iA], t0);
                    t1 = fmaf(v_s[iB], u_s[iB], t1);
                }
                float* bp = g_b_log + ((size_t)(b0 + b) * I_ + i_abs) * J_;
                if (MODE == 2) { t0 += bp[jA]; t1 += bp[jB]; }
                if (MODE == 1) { bp[jA] = t0;  bp[jB] = t1; }

                float m = fmaxf(t0, t1);
                #pragma unroll
                for (int off = 16; off; off >>= 1)
                    m = fmaxf(m, __shfl_xor_sync(0xffffffffu, m, off));
                float e0 = __expf(t0 - m);
                float e1 = __expf(t1 - m);
                float s  = e0 + e1;
                #pragma unroll
                for (int off = 16; off; off >>= 1)
                    s += __shfl_xor_sync(0xffffffffu, s, off);
                float inv = __fdividef(1.f, s);
                c_s[b * J_ + jA] = e0 * inv;
                c_s[b * J_ + jB] = e1 * inv;
            }
            __syncthreads();            // c_s ready

            // ---- phase D: s[b][j] += c[b][j] * u[b][j][lane] ----
            #pragma unroll
            for (int q = 0; q < 4; q++)
                #pragma unroll
                for (int e = 0; e < 2; e++) {
                    int j = q * 16 + w * 2 + e;
                    int sw = l ^ (j & 31);
                    #pragma unroll
                    for (int b = 0; b < BG; b++) {
                        float c = c_s[b * J_ + j];
                        float u = u_s[(b * J_ + j) * D_ + sw];
                        s_acc[b][q * 2 + e] = fmaf(c, u, s_acc[b][q * 2 + e]);
                    }
                }
            __syncthreads();            // protect u_s before next i's writes
        }
    }

    // ---- epilogue: write partial s (each warp owns disjoint (b,j) set) ----
    const float sc = (MODE == 0) ? (1.f / (float)J_) : 1.f;
    float* sp = g_s_part + (size_t)chunk * SLAB;
    #pragma unroll
    for (int q = 0; q < 4; q++)
        #pragma unroll
        for (int e = 0; e < 2; e++) {
            int j = q * 16 + w * 2 + e;
            #pragma unroll
            for (int b = 0; b < BG; b++)
                sp[((size_t)(b0 + b) * J_ + j) * D_ + l] = s_acc[b][q * 2 + e] * sc;
        }
}

// Sum the 64 chunk partials, squash, write v (and final output).
__global__ __launch_bounds__(256)
void squash_kernel(float* __restrict__ out)
{
    const int tid = threadIdx.x;
    const int w   = tid >> 5;
    const int l   = tid & 31;
    const int bj  = blockIdx.x * 8 + w;   // 0 .. B_*J_-1

    float s = 0.f;
    const float* p = g_s_part + (size_t)bj * D_ + l;
    #pragma unroll
    for (int ch = 0; ch < NCHUNK; ch++) s += p[(size_t)ch * SLAB];

    float sq = s * s;
    #pragma unroll
    for (int off = 16; off; off >>= 1)
        sq += __shfl_xor_sync(0xffffffffu, sq, off);

    float scale = sq / ((1.f + sq) * sqrtf(sq + 1e-7f));
    float v = scale * s;

    g_v[(size_t)bj * D_ + l] = v;
    if (out) out[(size_t)bj * D_ + l] = v;
}

extern "C" void kernel_launch(void* const* d_in, const int* in_sizes, int n_in,
                              void* d_out, int out_size)
{
    const float* x;
    const float* W;
    if (in_sizes[0] == B_ * I_ * KK) {
        x = (const float*)d_in[0];
        W = (const float*)d_in[1];
    } else {
        x = (const float*)d_in[1];
        W = (const float*)d_in[0];
    }
    float* out = (float*)d_out;

    cudaFuncSetAttribute(route_kernel<0>, cudaFuncAttributeMaxDynamicSharedMemorySize, SMB_M0);
    cudaFuncSetAttribute(route_kernel<1>, cudaFuncAttributeMaxDynamicSharedMemorySize, SMB_FULL);
    cudaFuncSetAttribute(route_kernel<2>, cudaFuncAttributeMaxDynamicSharedMemorySize, SMB_FULL);

    const dim3 grid(NBG * NCHUNK);   // 256 blocks
    const dim3 blk(THREADS);

    route_kernel<0><<<grid, blk, SMB_M0>>>(x, W);     // r=0
    squash_kernel<<<256, 256>>>(nullptr);             // v0

    route_kernel<1><<<grid, blk, SMB_FULL>>>(x, W);   // r=1
    squash_kernel<<<256, 256>>>(nullptr);             // v1

    route_kernel<2><<<grid, blk, SMB_FULL>>>(x, W);   // r=2
    squash_kernel<<<256, 256>>>(out);                 // v2 -> output
}